// round 15
// baseline (speedup 1.0000x reference)
#include <cuda_runtime.h>
#include <cuda_bf16.h>
#include <cstdint>

#define H      1024
#define H2     2048
#define VOCAB  32001
#define VPAD   32128   // 251 * 128 : padded cols of bf16 W2v AND logits staging
#define DEPTH  11
#define NODES  4095

// ---------------- scratch (static device globals: allowed) ----------------
__device__ __align__(16) __nv_bfloat16 g_h[NODES * H];            // node hiddens, BFS order
__device__ __align__(16) __nv_bfloat16 g_mid[(size_t)NODES * H2]; // sigmoid activations
__device__ __align__(16) __nv_bfloat16 g_W1c[H * H2];
__device__ __align__(16) __nv_bfloat16 g_W2c[H2 * H2];
__device__ __align__(16) __nv_bfloat16 g_W1v[H * H2];
__device__ __align__(16) __nv_bfloat16 g_W2v[(size_t)H2 * VPAD];  // [k][n] bf16, cols >= 32001 zero
__device__ __align__(16) __nv_bfloat16 g_logits[(size_t)NODES * VPAD]; // bf16 logits staging (preorder rows)
__device__ __align__(16) float         g_rowsum[NODES];           // sum(exp(logits)) per preorder row
__device__ __align__(16) float         g_part[2048 * 2048];       // split-K partial slabs (16MB)
__device__                int          g_cnt[256];                // split-K tile arrival counters

__device__ __forceinline__ uint32_t smem_u32(const void* p) {
    return (uint32_t)__cvta_generic_to_shared(p);
}

// pre-order position of BFS node j (perfect binary tree, levels 0..DEPTH)
__device__ __forceinline__ int preorder_row(int j) {
    int t = j + 1;
    int d = 31 - __clz(t);
    int p = t - (1 << d);
    int idx = 0;
    #pragma unroll 1
    for (int k = 0; k < d; ++k) {
        int b = (p >> (d - 1 - k)) & 1;
        idx += 1 + b * ((1 << (DEPTH - k)) - 1);
    }
    return idx;
}

// ============================================================================
// Proven mma.sync GEMM (vocab first layer).
// MODE 0: out = bf16(sigmoid(acc+bias)) -> (bf16*)outp, ld = N
// ============================================================================
constexpr int BM = 128;
constexpr int BN = 128;
constexpr int BK = 32;
constexpr int STAGES = 3;

template <int MODE>
__global__ void __launch_bounds__(256, 2)
gemm_bf16(const __nv_bfloat16* __restrict__ A, int lda,
          const __nv_bfloat16* __restrict__ B, int ldb,
          const float* __restrict__ bias,
          int M, int N, int K,
          void* outp, int child_off)
{
    __shared__ __align__(16) unsigned char smem[STAGES * 2 * 8192];

    const int tid  = threadIdx.x;
    const int wid  = tid >> 5;
    const int lane = tid & 31;
    const int wm   = wid & 3;
    const int wn   = wid >> 2;
    const int m0   = blockIdx.x * BM;
    const int n0   = blockIdx.y * BN;

    const uint32_t sA = smem_u32(smem);
    const uint32_t sB = sA + STAGES * 8192;

    float acc[2][8][4];
    #pragma unroll
    for (int i = 0; i < 2; ++i)
        #pragma unroll
        for (int j = 0; j < 8; ++j)
            #pragma unroll
            for (int q = 0; q < 4; ++q) acc[i][j][q] = 0.0f;

    auto load_stage = [&](int s, int k0) {
        #pragma unroll
        for (int t = 0; t < 2; ++t) {
            int q = tid + t * 256;
            int r = q >> 2, c = q & 3;
            uint32_t dst = sA + s * 8192 + r * 64 + ((c ^ ((r >> 1) & 3)) << 4);
            int gm = m0 + r;
            int sz = (gm < M) ? 16 : 0;
            if (gm >= M) gm = M - 1;
            const __nv_bfloat16* src = A + (size_t)gm * lda + k0 + c * 8;
            asm volatile("cp.async.cg.shared.global [%0], [%1], 16, %2;\n"
                         :: "r"(dst), "l"(src), "r"(sz));
        }
        #pragma unroll
        for (int t = 0; t < 2; ++t) {
            int q = tid + t * 256;
            int k = q >> 4, nc = q & 15;
            uint32_t dst = sB + s * 8192 + k * 256 + ((nc ^ (k & 7)) << 4);
            const __nv_bfloat16* src = B + (size_t)(k0 + k) * ldb + n0 + nc * 8;
            asm volatile("cp.async.cg.shared.global [%0], [%1], 16;\n"
                         :: "r"(dst), "l"(src));
        }
    };

    const int kiters = K >> 5;

    #pragma unroll
    for (int s = 0; s < STAGES - 1; ++s) {
        load_stage(s, s * BK);
        asm volatile("cp.async.commit_group;\n");
    }

    for (int it = 0; it < kiters; ++it) {
        asm volatile("cp.async.wait_group %0;\n" :: "n"(STAGES - 2));
        __syncthreads();
        {
            int pf = it + STAGES - 1;
            if (pf < kiters) load_stage(pf % STAGES, pf * BK);
            asm volatile("cp.async.commit_group;\n");
        }
        const uint32_t aBase = sA + (it % STAGES) * 8192;
        const uint32_t bBase = sB + (it % STAGES) * 8192;

        #pragma unroll
        for (int kk = 0; kk < 2; ++kk) {
            uint32_t a[2][4];
            #pragma unroll
            for (int i = 0; i < 2; ++i) {
                int r = wm * 32 + i * 16 + (lane & 15);
                int c = kk * 2 + (lane >> 4);
                uint32_t addr = aBase + r * 64 + ((c ^ ((r >> 1) & 3)) << 4);
                asm volatile("ldmatrix.sync.aligned.m8n8.x4.shared.b16 {%0,%1,%2,%3}, [%4];\n"
                             : "=r"(a[i][0]), "=r"(a[i][1]), "=r"(a[i][2]), "=r"(a[i][3])
                             : "r"(addr));
            }
            #pragma unroll
            for (int j2 = 0; j2 < 4; ++j2) {
                uint32_t b[4];
                int k  = kk * 16 + (lane & 15);
                int nc = wn * 8 + j2 * 2 + (lane >> 4);
                uint32_t addr = bBase + k * 256 + ((nc ^ (k & 7)) << 4);
                asm volatile("ldmatrix.sync.aligned.m8n8.x4.trans.shared.b16 {%0,%1,%2,%3}, [%4];\n"
                             : "=r"(b[0]), "=r"(b[1]), "=r"(b[2]), "=r"(b[3])
                             : "r"(addr));
                #pragma unroll
                for (int jj = 0; jj < 2; ++jj) {
                    int j = j2 * 2 + jj;
                    #pragma unroll
                    for (int i = 0; i < 2; ++i) {
                        asm volatile(
                            "mma.sync.aligned.m16n8k16.row.col.f32.bf16.bf16.f32 "
                            "{%0,%1,%2,%3}, {%4,%5,%6,%7}, {%8,%9}, {%0,%1,%2,%3};\n"
                            : "+f"(acc[i][j][0]), "+f"(acc[i][j][1]),
                              "+f"(acc[i][j][2]), "+f"(acc[i][j][3])
                            : "r"(a[i][0]), "r"(a[i][1]), "r"(a[i][2]), "r"(a[i][3]),
                              "r"(b[jj * 2]), "r"(b[jj * 2 + 1]));
                    }
                }
            }
        }
    }

    const int r0 = lane >> 2;
    const int cc = (lane & 3) * 2;
    #pragma unroll
    for (int i = 0; i < 2; ++i) {
        const int mbase = m0 + wm * 32 + i * 16;
        const int mA = mbase + r0;
        const int mB = mbase + r0 + 8;
        #pragma unroll
        for (int j = 0; j < 8; ++j) {
            const int n = n0 + wn * 64 + j * 8 + cc;
            float2 bb = *(const float2*)(bias + n);
            float v0 = acc[i][j][0] + bb.x, v1 = acc[i][j][1] + bb.y;
            float v2 = acc[i][j][2] + bb.x, v3 = acc[i][j][3] + bb.y;

            if (MODE == 0) {
                v0 = 1.0f / (1.0f + __expf(-v0));
                v1 = 1.0f / (1.0f + __expf(-v1));
                v2 = 1.0f / (1.0f + __expf(-v2));
                v3 = 1.0f / (1.0f + __expf(-v3));
                __nv_bfloat16* O = (__nv_bfloat16*)outp;
                if (mA < M) *(__nv_bfloat162*)(O + (size_t)mA * N + n) =
                    __nv_bfloat162(__float2bfloat16(v0), __float2bfloat16(v1));
                if (mB < M) *(__nv_bfloat162*)(O + (size_t)mB * N + n) =
                    __nv_bfloat162(__float2bfloat16(v2), __float2bfloat16(v3));
            } else {
                const int nodeb = child_off + (n >> 10);
                const int col   = n & (H - 1);
                if (mA < M) *(__nv_bfloat162*)&g_h[(size_t)(nodeb + 2 * mA) * H + col] =
                    __nv_bfloat162(__float2bfloat16(v0), __float2bfloat16(v1));
                if (mB < M) *(__nv_bfloat162*)&g_h[(size_t)(nodeb + 2 * mB) * H + col] =
                    __nv_bfloat162(__float2bfloat16(v2), __float2bfloat16(v3));
            }
        }
    }
}

// ============================================================================
// Split-K small-M GEMM for tree expansion with FUSED fixup:
// BM=64, BN=128, BK=32, 3 stages. grid (gx, 16, KS). Each CTA writes its
// K-chunk partial into slab z; the LAST CTA per (x,y) tile (atomic counter)
// sums all KS slabs + bias + activation and stores the final result.
// MODE0: sigmoid -> g_mid ; MODE1: child scatter -> g_h.
// ============================================================================
template <int MODE>
__global__ void __launch_bounds__(256)
smallgemm_fused(const __nv_bfloat16* __restrict__ A, int lda,
                const __nv_bfloat16* __restrict__ W,
                const float* __restrict__ bias,
                int M, int klen, int KS,
                float* __restrict__ part, int child_off)
{
    __shared__ __align__(16) unsigned char smem[STAGES * (4096 + 8192)];
    __shared__ int s_last;

    const int tid  = threadIdx.x;
    const int wid  = tid >> 5;
    const int lane = tid & 31;
    const int wm   = wid & 3;     // 4 strips x 16 rows
    const int wn   = wid >> 2;    // 2 strips x 64 cols
    const int m0   = blockIdx.x * 64;
    const int n0   = blockIdx.y * 128;
    const int z    = blockIdx.z;
    const int Mpad = gridDim.x * 64;
    const int k0g  = z * klen;

    const uint32_t sA = smem_u32(smem);
    const uint32_t sB = sA + STAGES * 4096;

    float acc[8][4];
    #pragma unroll
    for (int j = 0; j < 8; ++j)
        #pragma unroll
        for (int q = 0; q < 4; ++q) acc[j][q] = 0.0f;

    auto load_stage = [&](int s, int kl) {
        {
            int r = tid >> 2, c = tid & 3;
            uint32_t dst = sA + s * 4096 + r * 64 + ((c ^ ((r >> 1) & 3)) << 4);
            int gm = m0 + r;
            int sz = (gm < M) ? 16 : 0;
            if (gm >= M) gm = M - 1;
            const __nv_bfloat16* src = A + (size_t)gm * lda + k0g + kl + c * 8;
            asm volatile("cp.async.cg.shared.global [%0], [%1], 16, %2;\n"
                         :: "r"(dst), "l"(src), "r"(sz));
        }
        #pragma unroll
        for (int t = 0; t < 2; ++t) {
            int q = tid + t * 256;
            int k = q >> 4, nc = q & 15;
            uint32_t dst = sB + s * 8192 + k * 256 + ((nc ^ (k & 7)) << 4);
            const __nv_bfloat16* src = W + (size_t)(k0g + kl + k) * H2 + n0 + nc * 8;
            asm volatile("cp.async.cg.shared.global [%0], [%1], 16;\n"
                         :: "r"(dst), "l"(src));
        }
    };

    const int kiters = klen >> 5;

    load_stage(0, 0);
    asm volatile("cp.async.commit_group;\n");
    load_stage(1, BK);
    asm volatile("cp.async.commit_group;\n");

    for (int it = 0; it < kiters; ++it) {
        asm volatile("cp.async.wait_group 1;\n");
        __syncthreads();
        {
            int pf = it + 2;
            if (pf < kiters) load_stage(pf % STAGES, pf * BK);
            asm volatile("cp.async.commit_group;\n");
        }
        const uint32_t aBase = sA + (it % STAGES) * 4096;
        const uint32_t bBase = sB + (it % STAGES) * 8192;

        #pragma unroll
        for (int kk = 0; kk < 2; ++kk) {
            uint32_t a[4];
            {
                int r = wm * 16 + (lane & 15);
                int c = kk * 2 + (lane >> 4);
                uint32_t addr = aBase + r * 64 + ((c ^ ((r >> 1) & 3)) << 4);
                asm volatile("ldmatrix.sync.aligned.m8n8.x4.shared.b16 {%0,%1,%2,%3}, [%4];\n"
                             : "=r"(a[0]), "=r"(a[1]), "=r"(a[2]), "=r"(a[3])
                             : "r"(addr));
            }
            #pragma unroll
            for (int j2 = 0; j2 < 4; ++j2) {
                uint32_t b[4];
                int k  = kk * 16 + (lane & 15);
                int nc = wn * 8 + j2 * 2 + (lane >> 4);
                uint32_t addr = bBase + k * 256 + ((nc ^ (k & 7)) << 4);
                asm volatile("ldmatrix.sync.aligned.m8n8.x4.trans.shared.b16 {%0,%1,%2,%3}, [%4];\n"
                             : "=r"(b[0]), "=r"(b[1]), "=r"(b[2]), "=r"(b[3])
                             : "r"(addr));
                #pragma unroll
                for (int jj = 0; jj < 2; ++jj) {
                    int j = j2 * 2 + jj;
                    asm volatile(
                        "mma.sync.aligned.m16n8k16.row.col.f32.bf16.bf16.f32 "
                        "{%0,%1,%2,%3}, {%4,%5,%6,%7}, {%8,%9}, {%0,%1,%2,%3};\n"
                        : "+f"(acc[j][0]), "+f"(acc[j][1]), "+f"(acc[j][2]), "+f"(acc[j][3])
                        : "r"(a[0]), "r"(a[1]), "r"(a[2]), "r"(a[3]),
                          "r"(b[jj * 2]), "r"(b[jj * 2 + 1]));
                }
            }
        }
    }

    // write partial tile into slab z (rows beyond M are garbage, never read)
    {
        const int r0 = lane >> 2;
        const int cc = (lane & 3) * 2;
        const int rowA = m0 + wm * 16 + r0;
        const int rowB = rowA + 8;
        float* pA = part + ((size_t)z * Mpad + rowA) * H2;
        float* pB = part + ((size_t)z * Mpad + rowB) * H2;
        #pragma unroll
        for (int j = 0; j < 8; ++j) {
            const int n = n0 + wn * 64 + j * 8 + cc;
            *(float2*)(pA + n) = make_float2(acc[j][0], acc[j][1]);
            *(float2*)(pB + n) = make_float2(acc[j][2], acc[j][3]);
        }
    }

    // ---- fused split-K fixup: last CTA per (x,y) tile finalizes ----
    __threadfence();
    if (tid == 0) {
        int old = atomicAdd(&g_cnt[blockIdx.x * 16 + blockIdx.y], 1);
        s_last = (old == KS - 1) ? 1 : 0;
    }
    __syncthreads();
    if (!s_last) return;
    if (tid == 0) g_cnt[blockIdx.x * 16 + blockIdx.y] = 0;   // reset for next launch
    __threadfence();   // ensure other CTAs' partial stores are visible

    // finalize 64 rows x 128 cols (64 float2 per row); 4096 pairs / 256 threads
    for (int e = tid; e < 64 * 64; e += 256) {
        const int ml = e >> 6;            // local row
        const int m  = m0 + ml;
        if (m >= M) continue;
        const int n  = n0 + ((e & 63) << 1);
        float2 bb = *(const float2*)(bias + n);
        float v0 = bb.x, v1 = bb.y;
        for (int zz = 0; zz < KS; ++zz) {
            float2 pv = *(const float2*)(part + ((size_t)zz * Mpad + m) * H2 + n);
            v0 += pv.x; v1 += pv.y;
        }
        if (MODE == 0) {
            v0 = 1.0f / (1.0f + __expf(-v0));
            v1 = 1.0f / (1.0f + __expf(-v1));
            *(__nv_bfloat162*)&g_mid[(size_t)m * H2 + n] =
                __nv_bfloat162(__float2bfloat16(v0), __float2bfloat16(v1));
        } else {
            const int node = child_off + 2 * m + (n >> 10);
            const int col  = n & (H - 1);
            *(__nv_bfloat162*)&g_h[(size_t)node * H + col] =
                __nv_bfloat162(__float2bfloat16(v0), __float2bfloat16(v1));
        }
    }
}

// ============================================================================
// Logits GEMM (R13 winner): 128x128x64 tiles, 3-stage cp.async, 96KB dyn smem,
// 2 CTAs/SM. Epilogue: bias + bf16 store into padded staging (preorder rows)
// + fused sum(exp) atomics (plain __expf — MUFU is hidden under the mainloop).
// ============================================================================
constexpr int L_BK   = 64;
constexpr int L_AB   = BM * 128;                       // 16384 B / stage
constexpr int L_BB   = L_BK * 256;                     // 16384 B / stage
constexpr int L_SMEM = STAGES * (L_AB + L_BB);         // 98304

__global__ void __launch_bounds__(256, 2)
gemm_logits(const __nv_bfloat16* __restrict__ A,
            const __nv_bfloat16* __restrict__ B,
            const float* __restrict__ bias,
            __nv_bfloat16* __restrict__ lgout,
            float* __restrict__ rowsum)
{
    extern __shared__ __align__(16) unsigned char dsmem[];
    const int tid  = threadIdx.x;
    const int wid  = tid >> 5;
    const int lane = tid & 31;
    const int wm   = wid & 3;
    const int wn   = wid >> 2;
    const int m0   = blockIdx.x * BM;
    const int n0   = blockIdx.y * BN;
    const int M    = NODES;

    const uint32_t sA = smem_u32(dsmem);
    const uint32_t sB = sA + STAGES * L_AB;

    float acc[2][8][4];
    #pragma unroll
    for (int i = 0; i < 2; ++i)
        #pragma unroll
        for (int j = 0; j < 8; ++j)
            #pragma unroll
            for (int q = 0; q < 4; ++q) acc[i][j][q] = 0.0f;

    auto load_stage = [&](int s, int k0) {
        #pragma unroll
        for (int t = 0; t < 4; ++t) {
            int q = tid + t * 256;
            int r = q >> 3, c = q & 7;
            uint32_t dst = sA + s * L_AB + r * 128 + ((c ^ (r & 7)) << 4);
            int gm = m0 + r;
            if (gm >= M) gm = M - 1;
            const __nv_bfloat16* src = A + (size_t)gm * H2 + k0 + c * 8;
            asm volatile("cp.async.cg.shared.global [%0], [%1], 16;\n"
                         :: "r"(dst), "l"(src));
        }
        #pragma unroll
        for (int t = 0; t < 4; ++t) {
            int q = tid + t * 256;
            int k = q >> 4, nc = q & 15;
            uint32_t dst = sB + s * L_BB + k * 256 + ((nc ^ (k & 7)) << 4);
            const __nv_bfloat16* src = B + (size_t)(k0 + k) * VPAD + n0 + nc * 8;
            asm volatile("cp.async.cg.shared.global [%0], [%1], 16;\n"
                         :: "r"(dst), "l"(src));
        }
    };

    const int kiters = H2 / L_BK;   // 32

    load_stage(0, 0);
    asm volatile("cp.async.commit_group;\n");
    load_stage(1, L_BK);
    asm volatile("cp.async.commit_group;\n");

    for (int it = 0; it < kiters; ++it) {
        asm volatile("cp.async.wait_group 1;\n");
        __syncthreads();
        {
            int pf = it + 2;
            if (pf < kiters) load_stage(pf % STAGES, pf * L_BK);
            asm volatile("cp.async.commit_group;\n");
        }
        const uint32_t aBase = sA + (it % STAGES) * L_AB;
        const uint32_t bBase = sB + (it % STAGES) * L_BB;

        #pragma unroll
        for (int kk = 0; kk < 4; ++kk) {
            uint32_t a[2][4];
            #pragma unroll
            for (int i = 0; i < 2; ++i) {
                int r = wm * 32 + i * 16 + (lane & 15);
                int c = kk * 2 + (lane >> 4);
                uint32_t addr = aBase + r * 128 + ((c ^ (r & 7)) << 4);
                asm volatile("ldmatrix.sync.aligned.m8n8.x4.shared.b16 {%0,%1,%2,%3}, [%4];\n"
                             : "=r"(a[i][0]), "=r"(a[i][1]), "=r"(a[i][2]), "=r"(a[i][3])
                             : "r"(addr));
            }
            #pragma unroll
            for (int j2 = 0; j2 < 4; ++j2) {
                uint32_t b[4];
                int k  = kk * 16 + (lane & 15);
                int nc = wn * 8 + j2 * 2 + (lane >> 4);
                uint32_t addr = bBase + k * 256 + ((nc ^ (k & 7)) << 4);
                asm volatile("ldmatrix.sync.aligned.m8n8.x4.trans.shared.b16 {%0,%1,%2,%3}, [%4];\n"
                             : "=r"(b[0]), "=r"(b[1]), "=r"(b[2]), "=r"(b[3])
                             : "r"(addr));
                #pragma unroll
                for (int jj = 0; jj < 2; ++jj) {
                    int j = j2 * 2 + jj;
                    #pragma unroll
                    for (int i = 0; i < 2; ++i) {
                        asm volatile(
                            "mma.sync.aligned.m16n8k16.row.col.f32.bf16.bf16.f32 "
                            "{%0,%1,%2,%3}, {%4,%5,%6,%7}, {%8,%9}, {%0,%1,%2,%3};\n"
                            : "+f"(acc[i][j][0]), "+f"(acc[i][j][1]),
                              "+f"(acc[i][j][2]), "+f"(acc[i][j][3])
                            : "r"(a[i][0]), "r"(a[i][1]), "r"(a[i][2]), "r"(a[i][3]),
                              "r"(b[jj * 2]), "r"(b[jj * 2 + 1]));
                    }
                }
            }
        }
    }

    const int r0 = lane >> 2;
    const int cc = (lane & 3) * 2;
    #pragma unroll
    for (int i = 0; i < 2; ++i) {
        const int mbase = m0 + wm * 32 + i * 16;
        const int mA = mbase + r0;
        const int mB = mbase + r0 + 8;
        const bool vA = (mA < M), vB = (mB < M);
        const int prA = vA ? preorder_row(mA) : 0;
        const int prB = vB ? preorder_row(mB) : 0;
        __nv_bfloat16* oA = lgout + (size_t)prA * VPAD;
        __nv_bfloat16* oB = lgout + (size_t)prB * VPAD;
        float eA = 0.0f, eB = 0.0f;
        #pragma unroll
        for (int j = 0; j < 8; ++j) {
            const int n = n0 + wn * 64 + j * 8 + cc;     // always < VPAD, even
            const bool g0 = (n < VOCAB), g1 = (n + 1 < VOCAB);
            const float bv0 = g0 ? __ldg(bias + n)     : 0.0f;
            const float bv1 = g1 ? __ldg(bias + n + 1) : 0.0f;
            float v0 = acc[i][j][0] + bv0, v1 = acc[i][j][1] + bv1;
            float v2 = acc[i][j][2] + bv0, v3 = acc[i][j][3] + bv1;
            if (vA) {
                *(__nv_bfloat162*)(oA + n) =
                    __nv_bfloat162(__float2bfloat16(v0), __float2bfloat16(v1));
                if (g0) eA += __expf(v0);
                if (g1) eA += __expf(v1);
            }
            if (vB) {
                *(__nv_bfloat162*)(oB + n) =
                    __nv_bfloat162(__float2bfloat16(v2), __float2bfloat16(v3));
                if (g0) eB += __expf(v2);
                if (g1) eB += __expf(v3);
            }
        }
        eA += __shfl_xor_sync(0xffffffffu, eA, 1);
        eA += __shfl_xor_sync(0xffffffffu, eA, 2);
        eB += __shfl_xor_sync(0xffffffffu, eB, 1);
        eB += __shfl_xor_sync(0xffffffffu, eB, 2);
        if ((lane & 3) == 0) {
            if (vA) atomicAdd(rowsum + prA, eA);
            if (vB) atomicAdd(rowsum + prB, eB);
        }
    }
}

// ---------------- small kernels (vectorized) ----------------
__global__ void cvt_root_kernel(const float* __restrict__ root) {
    int i = blockIdx.x * 256 + threadIdx.x;
    if (i < H) g_h[i] = __float2bfloat16(root[i]);
    if (blockIdx.x == 0) {
        for (int r = threadIdx.x; r < NODES; r += 256) g_rowsum[r] = 0.0f;
        if (threadIdx.x < 256) g_cnt[threadIdx.x] = 0;
    }
}

// 8 elems/thread: 2x float4 load, 1x uint4 store (n divisible by 8, src contiguous)
__global__ void cvt_w8_kernel(const float* __restrict__ src, __nv_bfloat16* __restrict__ dst, int n) {
    int i = (blockIdx.x * 256 + threadIdx.x) * 8;
    if (i < n) {
        float4 v0 = *(const float4*)(src + i);
        float4 v1 = *(const float4*)(src + i + 4);
        __nv_bfloat162 p0(__float2bfloat16(v0.x), __float2bfloat16(v0.y));
        __nv_bfloat162 p1(__float2bfloat16(v0.z), __float2bfloat16(v0.w));
        __nv_bfloat162 p2(__float2bfloat16(v1.x), __float2bfloat16(v1.y));
        __nv_bfloat162 p3(__float2bfloat16(v1.z), __float2bfloat16(v1.w));
        uint4 o;
        o.x = *(uint32_t*)&p0; o.y = *(uint32_t*)&p1;
        o.z = *(uint32_t*)&p2; o.w = *(uint32_t*)&p3;
        *(uint4*)(dst + i) = o;
    }
}

// pad-convert W2v: [2048, 32001] fp32 -> [2048, VPAD] bf16, 8 elems/thread.
// src row stride 32001 (odd) -> loads MUST be scalar (still coalesced).
__global__ void cvt_pad8_kernel(const float* __restrict__ src, __nv_bfloat16* __restrict__ dst) {
    const int CPR = VPAD / 8;                  // chunks per row = 4016
    int p = blockIdx.x * 256 + threadIdx.x;
    if (p >= H2 * CPR) return;
    int r = p / CPR, pc = p - r * CPR;
    int c = pc * 8;
    const float* srow = src + (size_t)r * VOCAB;
    float v[8];
    #pragma unroll
    for (int t = 0; t < 8; ++t) v[t] = (c + t < VOCAB) ? srow[c + t] : 0.0f;
    __nv_bfloat162 p0(__float2bfloat16(v[0]), __float2bfloat16(v[1]));
    __nv_bfloat162 p1(__float2bfloat16(v[2]), __float2bfloat16(v[3]));
    __nv_bfloat162 p2(__float2bfloat16(v[4]), __float2bfloat16(v[5]));
    __nv_bfloat162 p3(__float2bfloat16(v[6]), __float2bfloat16(v[7]));
    uint4 o;
    o.x = *(uint32_t*)&p0; o.y = *(uint32_t*)&p1;
    o.z = *(uint32_t*)&p2; o.w = *(uint32_t*)&p3;
    *(uint4*)(dst + (size_t)r * VPAD + c) = o;
}

// out[r][i] = bf16_logits[r][i] - log(rowsum[r]) ; sole writer of d_out.
__global__ void __launch_bounds__(256)
lse_sub_kernel(const __nv_bfloat16* __restrict__ lg, float* __restrict__ out,
               const float* __restrict__ rowsum) {
    const int r = blockIdx.x;
    const float lse = logf(rowsum[r]);
    const __nv_bfloat16* src = lg + (size_t)r * VPAD;
    float* p = out + (size_t)r * VOCAB;
    const int tid = threadIdx.x;
    const int head = (4 - (int)(((size_t)r * VOCAB) & 3)) & 3;
    if (tid < head) p[tid] = __bfloat162float(src[tid]) - lse;
    const int nf4 = (VOCAB - head) >> 2;
    float4* p4 = (float4*)(p + head);
    for (int i = tid; i < nf4; i += 256) {
        const int o = head + i * 4;
        float4 v;
        v.x = __bfloat162float(src[o])     - lse;
        v.y = __bfloat162float(src[o + 1]) - lse;
        v.z = __bfloat162float(src[o + 2]) - lse;
        v.w = __bfloat162float(src[o + 3]) - lse;
        p4[i] = v;
    }
    const int done = head + nf4 * 4;
    if (tid < VOCAB - done) p[done + tid] = __bfloat162float(src[done + tid]) - lse;
}

// ---------------- launch ----------------
extern "C" void kernel_launch(void* const* d_in, const int* in_sizes, int n_in,
                              void* d_out, int out_size) {
    (void)in_sizes; (void)n_in; (void)out_size;
    const float* root = (const float*)d_in[0];
    const float* W1v  = (const float*)d_in[1];
    const float* b1v  = (const float*)d_in[2];
    const float* W2v  = (const float*)d_in[3];
    const float* b2v  = (const float*)d_in[4];
    const float* W1c  = (const float*)d_in[5];
    const float* b1c  = (const float*)d_in[6];
    const float* W2c  = (const float*)d_in[7];
    const float* b2c  = (const float*)d_in[8];

    void* pa;
    cudaGetSymbolAddress(&pa, g_h);      __nv_bfloat16* g_h_p    = (__nv_bfloat16*)pa;
    cudaGetSymbolAddress(&pa, g_mid);    __nv_bfloat16* g_mid_p  = (__nv_bfloat16*)pa;
    cudaGetSymbolAddress(&pa, g_W1c);    __nv_bfloat16* W1c_b    = (__nv_bfloat16*)pa;
    cudaGetSymbolAddress(&pa, g_W2c);    __nv_bfloat16* W2c_b    = (__nv_bfloat16*)pa;
    cudaGetSymbolAddress(&pa, g_W1v);    __nv_bfloat16* W1v_b    = (__nv_bfloat16*)pa;
    cudaGetSymbolAddress(&pa, g_W2v);    __nv_bfloat16* W2v_b    = (__nv_bfloat16*)pa;
    cudaGetSymbolAddress(&pa, g_logits); __nv_bfloat16* lg_p     = (__nv_bfloat16*)pa;
    cudaGetSymbolAddress(&pa, g_rowsum); float*         rowsum_p = (float*)pa;
    cudaGetSymbolAddress(&pa, g_part);   float*         part_p   = (float*)pa;

    cudaFuncSetAttribute(gemm_logits, cudaFuncAttributeMaxDynamicSharedMemorySize, L_SMEM);

    cvt_root_kernel<<<4, 256>>>(root);
    cvt_w8_kernel<<<(H * H2 / 8 + 255) / 256, 256>>>(W1c, W1c_b, H * H2);
    cvt_w8_kernel<<<(H2 * H2 / 8 + 255) / 256, 256>>>(W2c, W2c_b, H2 * H2);
    cvt_w8_kernel<<<(H * H2 / 8 + 255) / 256, 256>>>(W1v, W1v_b, H * H2);
    cvt_pad8_kernel<<<(H2 * (VPAD / 8) + 255) / 256, 256>>>(W2v, W2v_b);

    // ---- tree expansion via split-K small GEMMs with fused fixup ----
    int off = 0;
    for (int d = 0; d < DEPTH; ++d) {
        const int R  = 1 << d;
        const int gx = (R + 63) / 64;
        int ks = 512 / (gx * 16);
        if (ks < 1) ks = 1;
        if (ks > 8) ks = 8;

        smallgemm_fused<0><<<dim3(gx, 16, ks), 256>>>(g_h_p + (size_t)off * H, H,
                                                      W1c_b, b1c, R, H / ks, ks,
                                                      part_p, 0);
        smallgemm_fused<1><<<dim3(gx, 16, ks), 256>>>(g_mid_p, H2,
                                                      W2c_b, b2c, R, H2 / ks, ks,
                                                      part_p, 2 * off + 1);
        off = 2 * off + 1;
    }

    // ---- vocab first layer for all nodes ----
    {
        dim3 grid((NODES + BM - 1) / BM, H2 / BN);
        gemm_bf16<0><<<grid, 256>>>(g_h_p, H, W1v_b, H2, b1v,
                                    NODES, H2, H, g_mid_p, 0);
    }

    // ---- logits GEMM -> bf16 staging + rowsum ----
    {
        dim3 grid((NODES + BM - 1) / BM, VPAD / BN);
        gemm_logits<<<grid, 256, L_SMEM>>>(g_mid_p, W2v_b, b2v,
                                           lg_p, rowsum_p);
    }

    // ---- final: out = logits - log-sum-exp (writes all of d_out) ----
    lse_sub_kernel<<<NODES, 256>>>(lg_p, (float*)d_out, rowsum_p);
}

// round 16
// speedup vs baseline: 1.0582x; 1.0582x over previous
#include <cuda_runtime.h>
#include <cuda_bf16.h>
#include <cstdint>

#define H      1024
#define H2     2048
#define VOCAB  32001
#define VPAD   32128   // 251 * 128 : padded cols of bf16 W2v AND logits staging
#define DEPTH  11
#define NODES  4095

// ---------------- scratch (static device globals: allowed) ----------------
__device__ __align__(16) __nv_bfloat16 g_h[NODES * H];            // node hiddens, BFS order
__device__ __align__(16) __nv_bfloat16 g_mid[(size_t)NODES * H2]; // sigmoid activations
__device__ __align__(16) __nv_bfloat16 g_W1c[H * H2];
__device__ __align__(16) __nv_bfloat16 g_W2c[H2 * H2];
__device__ __align__(16) __nv_bfloat16 g_W1v[H * H2];
__device__ __align__(16) __nv_bfloat16 g_W2v[(size_t)H2 * VPAD];  // [k][n] bf16, cols >= 32001 zero
__device__ __align__(16) __nv_bfloat16 g_logits[(size_t)NODES * VPAD]; // bf16 logits staging (preorder rows)
__device__ __align__(16) float         g_rowsum[NODES];           // sum(exp(logits)) per preorder row
__device__ __align__(16) float         g_part[2048 * 2048];       // split-K partial slabs (16MB)

__device__ __forceinline__ uint32_t smem_u32(const void* p) {
    return (uint32_t)__cvta_generic_to_shared(p);
}

// pre-order position of BFS node j (perfect binary tree, levels 0..DEPTH)
__device__ __forceinline__ int preorder_row(int j) {
    int t = j + 1;
    int d = 31 - __clz(t);
    int p = t - (1 << d);
    int idx = 0;
    #pragma unroll 1
    for (int k = 0; k < d; ++k) {
        int b = (p >> (d - 1 - k)) & 1;
        idx += 1 + b * ((1 << (DEPTH - k)) - 1);
    }
    return idx;
}

constexpr int BM = 128;
constexpr int BN = 128;
constexpr int BK = 32;
constexpr int STAGES = 3;

// ============================================================================
// Split-K small-M GEMM for tree expansion: BM=64, BN=128, BK=32, 3 stages.
// grid (ceil(R/64), 16, KS); each CTA computes its K-chunk partial into
// g_part slab z (no atomics). finalize<MODE> sums slabs + bias + activation.
// ============================================================================
__global__ void __launch_bounds__(256)
smallgemm(const __nv_bfloat16* __restrict__ A, int lda,
          const __nv_bfloat16* __restrict__ W,
          int M, int klen, float* __restrict__ part)
{
    __shared__ __align__(16) unsigned char smem[STAGES * (4096 + 8192)];

    const int tid  = threadIdx.x;
    const int wid  = tid >> 5;
    const int lane = tid & 31;
    const int wm   = wid & 3;     // 4 strips x 16 rows
    const int wn   = wid >> 2;    // 2 strips x 64 cols
    const int m0   = blockIdx.x * 64;
    const int n0   = blockIdx.y * 128;
    const int z    = blockIdx.z;
    const int Mpad = gridDim.x * 64;
    const int k0g  = z * klen;

    const uint32_t sA = smem_u32(smem);
    const uint32_t sB = sA + STAGES * 4096;

    float acc[8][4];
    #pragma unroll
    for (int j = 0; j < 8; ++j)
        #pragma unroll
        for (int q = 0; q < 4; ++q) acc[j][q] = 0.0f;

    auto load_stage = [&](int s, int kl) {
        {
            int r = tid >> 2, c = tid & 3;
            uint32_t dst = sA + s * 4096 + r * 64 + ((c ^ ((r >> 1) & 3)) << 4);
            int gm = m0 + r;
            int sz = (gm < M) ? 16 : 0;
            if (gm >= M) gm = M - 1;
            const __nv_bfloat16* src = A + (size_t)gm * lda + k0g + kl + c * 8;
            asm volatile("cp.async.cg.shared.global [%0], [%1], 16, %2;\n"
                         :: "r"(dst), "l"(src), "r"(sz));
        }
        #pragma unroll
        for (int t = 0; t < 2; ++t) {
            int q = tid + t * 256;
            int k = q >> 4, nc = q & 15;
            uint32_t dst = sB + s * 8192 + k * 256 + ((nc ^ (k & 7)) << 4);
            const __nv_bfloat16* src = W + (size_t)(k0g + kl + k) * H2 + n0 + nc * 8;
            asm volatile("cp.async.cg.shared.global [%0], [%1], 16;\n"
                         :: "r"(dst), "l"(src));
        }
    };

    const int kiters = klen >> 5;

    load_stage(0, 0);
    asm volatile("cp.async.commit_group;\n");
    load_stage(1, BK);
    asm volatile("cp.async.commit_group;\n");

    for (int it = 0; it < kiters; ++it) {
        asm volatile("cp.async.wait_group 1;\n");
        __syncthreads();
        {
            int pf = it + 2;
            if (pf < kiters) load_stage(pf % STAGES, pf * BK);
            asm volatile("cp.async.commit_group;\n");
        }
        const uint32_t aBase = sA + (it % STAGES) * 4096;
        const uint32_t bBase = sB + (it % STAGES) * 8192;

        #pragma unroll
        for (int kk = 0; kk < 2; ++kk) {
            uint32_t a[4];
            {
                int r = wm * 16 + (lane & 15);
                int c = kk * 2 + (lane >> 4);
                uint32_t addr = aBase + r * 64 + ((c ^ ((r >> 1) & 3)) << 4);
                asm volatile("ldmatrix.sync.aligned.m8n8.x4.shared.b16 {%0,%1,%2,%3}, [%4];\n"
                             : "=r"(a[0]), "=r"(a[1]), "=r"(a[2]), "=r"(a[3])
                             : "r"(addr));
            }
            #pragma unroll
            for (int j2 = 0; j2 < 4; ++j2) {
                uint32_t b[4];
                int k  = kk * 16 + (lane & 15);
                int nc = wn * 8 + j2 * 2 + (lane >> 4);
                uint32_t addr = bBase + k * 256 + ((nc ^ (k & 7)) << 4);
                asm volatile("ldmatrix.sync.aligned.m8n8.x4.trans.shared.b16 {%0,%1,%2,%3}, [%4];\n"
                             : "=r"(b[0]), "=r"(b[1]), "=r"(b[2]), "=r"(b[3])
                             : "r"(addr));
                #pragma unroll
                for (int jj = 0; jj < 2; ++jj) {
                    int j = j2 * 2 + jj;
                    asm volatile(
                        "mma.sync.aligned.m16n8k16.row.col.f32.bf16.bf16.f32 "
                        "{%0,%1,%2,%3}, {%4,%5,%6,%7}, {%8,%9}, {%0,%1,%2,%3};\n"
                        : "+f"(acc[j][0]), "+f"(acc[j][1]), "+f"(acc[j][2]), "+f"(acc[j][3])
                        : "r"(a[0]), "r"(a[1]), "r"(a[2]), "r"(a[3]),
                          "r"(b[jj * 2]), "r"(b[jj * 2 + 1]));
                }
            }
        }
    }

    const int r0 = lane >> 2;
    const int cc = (lane & 3) * 2;
    const int rowA = m0 + wm * 16 + r0;
    const int rowB = rowA + 8;
    float* pA = part + ((size_t)z * Mpad + rowA) * H2;
    float* pB = part + ((size_t)z * Mpad + rowB) * H2;
    #pragma unroll
    for (int j = 0; j < 8; ++j) {
        const int n = n0 + wn * 64 + j * 8 + cc;
        *(float2*)(pA + n) = make_float2(acc[j][0], acc[j][1]);
        *(float2*)(pB + n) = make_float2(acc[j][2], acc[j][3]);
    }
}

// sum KS slabs + bias, then MODE0: sigmoid -> g_mid ; MODE1: child scatter -> g_h
template <int MODE>
__global__ void __launch_bounds__(256)
finalize(const float* __restrict__ part, int KS, int Mpad,
         const float* __restrict__ bias, int R, int child_off)
{
    int idx = blockIdx.x * 256 + threadIdx.x;   // one thread per 2 cols
    if (idx >= R * (H2 / 2)) return;
    int m = idx / (H2 / 2);
    int n = (idx - m * (H2 / 2)) * 2;
    float2 bb = *(const float2*)(bias + n);
    float v0 = bb.x, v1 = bb.y;
    for (int zz = 0; zz < KS; ++zz) {
        float2 pv = *(const float2*)(part + ((size_t)zz * Mpad + m) * H2 + n);
        v0 += pv.x; v1 += pv.y;
    }
    if (MODE == 0) {
        v0 = 1.0f / (1.0f + __expf(-v0));
        v1 = 1.0f / (1.0f + __expf(-v1));
        *(__nv_bfloat162*)&g_mid[(size_t)m * H2 + n] =
            __nv_bfloat162(__float2bfloat16(v0), __float2bfloat16(v1));
    } else {
        const int node = child_off + 2 * m + (n >> 10);
        const int col  = n & (H - 1);
        *(__nv_bfloat162*)&g_h[(size_t)node * H + col] =
            __nv_bfloat162(__float2bfloat16(v0), __float2bfloat16(v1));
    }
}

// ============================================================================
// BK=64 GEMM structure shared by vocab-L1 and logits (3-stage cp.async,
// 96KB dynamic smem, 2 CTAs/SM, 128x128 tiles, four k16 steps per iter).
// ============================================================================
constexpr int L_BK   = 64;
constexpr int L_AB   = BM * 128;                       // 16384 B / stage
constexpr int L_BB   = L_BK * 256;                     // 16384 B / stage
constexpr int L_SMEM = STAGES * (L_AB + L_BB);         // 98304

// vocab first layer: g_mid = sigmoid(g_h @ W1v + b1v). K=1024 (16 iters), N=2048.
__global__ void __launch_bounds__(256, 2)
gemm_mid64(const __nv_bfloat16* __restrict__ A,       // g_h [NODES, 1024]
           const __nv_bfloat16* __restrict__ B,       // W1v [1024, 2048]
           const float* __restrict__ bias,
           __nv_bfloat16* __restrict__ outp)          // g_mid [NODES, 2048]
{
    extern __shared__ __align__(16) unsigned char dsmem[];
    const int tid  = threadIdx.x;
    const int wid  = tid >> 5;
    const int lane = tid & 31;
    const int wm   = wid & 3;
    const int wn   = wid >> 2;
    const int m0   = blockIdx.x * BM;
    const int n0   = blockIdx.y * BN;
    const int M    = NODES;

    const uint32_t sA = smem_u32(dsmem);
    const uint32_t sB = sA + STAGES * L_AB;

    float acc[2][8][4];
    #pragma unroll
    for (int i = 0; i < 2; ++i)
        #pragma unroll
        for (int j = 0; j < 8; ++j)
            #pragma unroll
            for (int q = 0; q < 4; ++q) acc[i][j][q] = 0.0f;

    auto load_stage = [&](int s, int k0) {
        #pragma unroll
        for (int t = 0; t < 4; ++t) {
            int q = tid + t * 256;
            int r = q >> 3, c = q & 7;
            uint32_t dst = sA + s * L_AB + r * 128 + ((c ^ (r & 7)) << 4);
            int gm = m0 + r;
            if (gm >= M) gm = M - 1;
            const __nv_bfloat16* src = A + (size_t)gm * H + k0 + c * 8;
            asm volatile("cp.async.cg.shared.global [%0], [%1], 16;\n"
                         :: "r"(dst), "l"(src));
        }
        #pragma unroll
        for (int t = 0; t < 4; ++t) {
            int q = tid + t * 256;
            int k = q >> 4, nc = q & 15;
            uint32_t dst = sB + s * L_BB + k * 256 + ((nc ^ (k & 7)) << 4);
            const __nv_bfloat16* src = B + (size_t)(k0 + k) * H2 + n0 + nc * 8;
            asm volatile("cp.async.cg.shared.global [%0], [%1], 16;\n"
                         :: "r"(dst), "l"(src));
        }
    };

    const int kiters = H / L_BK;   // 16

    load_stage(0, 0);
    asm volatile("cp.async.commit_group;\n");
    load_stage(1, L_BK);
    asm volatile("cp.async.commit_group;\n");

    for (int it = 0; it < kiters; ++it) {
        asm volatile("cp.async.wait_group 1;\n");
        __syncthreads();
        {
            int pf = it + 2;
            if (pf < kiters) load_stage(pf % STAGES, pf * L_BK);
            asm volatile("cp.async.commit_group;\n");
        }
        const uint32_t aBase = sA + (it % STAGES) * L_AB;
        const uint32_t bBase = sB + (it % STAGES) * L_BB;

        #pragma unroll
        for (int kk = 0; kk < 4; ++kk) {
            uint32_t a[2][4];
            #pragma unroll
            for (int i = 0; i < 2; ++i) {
                int r = wm * 32 + i * 16 + (lane & 15);
                int c = kk * 2 + (lane >> 4);
                uint32_t addr = aBase + r * 128 + ((c ^ (r & 7)) << 4);
                asm volatile("ldmatrix.sync.aligned.m8n8.x4.shared.b16 {%0,%1,%2,%3}, [%4];\n"
                             : "=r"(a[i][0]), "=r"(a[i][1]), "=r"(a[i][2]), "=r"(a[i][3])
                             : "r"(addr));
            }
            #pragma unroll
            for (int j2 = 0; j2 < 4; ++j2) {
                uint32_t b[4];
                int k  = kk * 16 + (lane & 15);
                int nc = wn * 8 + j2 * 2 + (lane >> 4);
                uint32_t addr = bBase + k * 256 + ((nc ^ (k & 7)) << 4);
                asm volatile("ldmatrix.sync.aligned.m8n8.x4.trans.shared.b16 {%0,%1,%2,%3}, [%4];\n"
                             : "=r"(b[0]), "=r"(b[1]), "=r"(b[2]), "=r"(b[3])
                             : "r"(addr));
                #pragma unroll
                for (int jj = 0; jj < 2; ++jj) {
                    int j = j2 * 2 + jj;
                    #pragma unroll
                    for (int i = 0; i < 2; ++i) {
                        asm volatile(
                            "mma.sync.aligned.m16n8k16.row.col.f32.bf16.bf16.f32 "
                            "{%0,%1,%2,%3}, {%4,%5,%6,%7}, {%8,%9}, {%0,%1,%2,%3};\n"
                            : "+f"(acc[i][j][0]), "+f"(acc[i][j][1]),
                              "+f"(acc[i][j][2]), "+f"(acc[i][j][3])
                            : "r"(a[i][0]), "r"(a[i][1]), "r"(a[i][2]), "r"(a[i][3]),
                              "r"(b[jj * 2]), "r"(b[jj * 2 + 1]));
                    }
                }
            }
        }
    }

    const int r0 = lane >> 2;
    const int cc = (lane & 3) * 2;
    #pragma unroll
    for (int i = 0; i < 2; ++i) {
        const int mbase = m0 + wm * 32 + i * 16;
        const int mA = mbase + r0;
        const int mB = mbase + r0 + 8;
        #pragma unroll
        for (int j = 0; j < 8; ++j) {
            const int n = n0 + wn * 64 + j * 8 + cc;      // always < H2
            float2 bb = *(const float2*)(bias + n);
            float v0 = acc[i][j][0] + bb.x, v1 = acc[i][j][1] + bb.y;
            float v2 = acc[i][j][2] + bb.x, v3 = acc[i][j][3] + bb.y;
            v0 = 1.0f / (1.0f + __expf(-v0));
            v1 = 1.0f / (1.0f + __expf(-v1));
            v2 = 1.0f / (1.0f + __expf(-v2));
            v3 = 1.0f / (1.0f + __expf(-v3));
            if (mA < M) *(__nv_bfloat162*)(outp + (size_t)mA * H2 + n) =
                __nv_bfloat162(__float2bfloat16(v0), __float2bfloat16(v1));
            if (mB < M) *(__nv_bfloat162*)(outp + (size_t)mB * H2 + n) =
                __nv_bfloat162(__float2bfloat16(v2), __float2bfloat16(v3));
        }
    }
}

// Logits GEMM (R13 winner): epilogue bias + bf16 store to padded staging
// (preorder rows) + fused sum(exp) atomics (plain __expf; hidden under mainloop).
__global__ void __launch_bounds__(256, 2)
gemm_logits(const __nv_bfloat16* __restrict__ A,
            const __nv_bfloat16* __restrict__ B,
            const float* __restrict__ bias,
            __nv_bfloat16* __restrict__ lgout,
            float* __restrict__ rowsum)
{
    extern __shared__ __align__(16) unsigned char dsmem[];
    const int tid  = threadIdx.x;
    const int wid  = tid >> 5;
    const int lane = tid & 31;
    const int wm   = wid & 3;
    const int wn   = wid >> 2;
    const int m0   = blockIdx.x * BM;
    const int n0   = blockIdx.y * BN;
    const int M    = NODES;

    const uint32_t sA = smem_u32(dsmem);
    const uint32_t sB = sA + STAGES * L_AB;

    float acc[2][8][4];
    #pragma unroll
    for (int i = 0; i < 2; ++i)
        #pragma unroll
        for (int j = 0; j < 8; ++j)
            #pragma unroll
            for (int q = 0; q < 4; ++q) acc[i][j][q] = 0.0f;

    auto load_stage = [&](int s, int k0) {
        #pragma unroll
        for (int t = 0; t < 4; ++t) {
            int q = tid + t * 256;
            int r = q >> 3, c = q & 7;
            uint32_t dst = sA + s * L_AB + r * 128 + ((c ^ (r & 7)) << 4);
            int gm = m0 + r;
            if (gm >= M) gm = M - 1;
            const __nv_bfloat16* src = A + (size_t)gm * H2 + k0 + c * 8;
            asm volatile("cp.async.cg.shared.global [%0], [%1], 16;\n"
                         :: "r"(dst), "l"(src));
        }
        #pragma unroll
        for (int t = 0; t < 4; ++t) {
            int q = tid + t * 256;
            int k = q >> 4, nc = q & 15;
            uint32_t dst = sB + s * L_BB + k * 256 + ((nc ^ (k & 7)) << 4);
            const __nv_bfloat16* src = B + (size_t)(k0 + k) * VPAD + n0 + nc * 8;
            asm volatile("cp.async.cg.shared.global [%0], [%1], 16;\n"
                         :: "r"(dst), "l"(src));
        }
    };

    const int kiters = H2 / L_BK;   // 32

    load_stage(0, 0);
    asm volatile("cp.async.commit_group;\n");
    load_stage(1, L_BK);
    asm volatile("cp.async.commit_group;\n");

    for (int it = 0; it < kiters; ++it) {
        asm volatile("cp.async.wait_group 1;\n");
        __syncthreads();
        {
            int pf = it + 2;
            if (pf < kiters) load_stage(pf % STAGES, pf * L_BK);
            asm volatile("cp.async.commit_group;\n");
        }
        const uint32_t aBase = sA + (it % STAGES) * L_AB;
        const uint32_t bBase = sB + (it % STAGES) * L_BB;

        #pragma unroll
        for (int kk = 0; kk < 4; ++kk) {
            uint32_t a[2][4];
            #pragma unroll
            for (int i = 0; i < 2; ++i) {
                int r = wm * 32 + i * 16 + (lane & 15);
                int c = kk * 2 + (lane >> 4);
                uint32_t addr = aBase + r * 128 + ((c ^ (r & 7)) << 4);
                asm volatile("ldmatrix.sync.aligned.m8n8.x4.shared.b16 {%0,%1,%2,%3}, [%4];\n"
                             : "=r"(a[i][0]), "=r"(a[i][1]), "=r"(a[i][2]), "=r"(a[i][3])
                             : "r"(addr));
            }
            #pragma unroll
            for (int j2 = 0; j2 < 4; ++j2) {
                uint32_t b[4];
                int k  = kk * 16 + (lane & 15);
                int nc = wn * 8 + j2 * 2 + (lane >> 4);
                uint32_t addr = bBase + k * 256 + ((nc ^ (k & 7)) << 4);
                asm volatile("ldmatrix.sync.aligned.m8n8.x4.trans.shared.b16 {%0,%1,%2,%3}, [%4];\n"
                             : "=r"(b[0]), "=r"(b[1]), "=r"(b[2]), "=r"(b[3])
                             : "r"(addr));
                #pragma unroll
                for (int jj = 0; jj < 2; ++jj) {
                    int j = j2 * 2 + jj;
                    #pragma unroll
                    for (int i = 0; i < 2; ++i) {
                        asm volatile(
                            "mma.sync.aligned.m16n8k16.row.col.f32.bf16.bf16.f32 "
                            "{%0,%1,%2,%3}, {%4,%5,%6,%7}, {%8,%9}, {%0,%1,%2,%3};\n"
                            : "+f"(acc[i][j][0]), "+f"(acc[i][j][1]),
                              "+f"(acc[i][j][2]), "+f"(acc[i][j][3])
                            : "r"(a[i][0]), "r"(a[i][1]), "r"(a[i][2]), "r"(a[i][3]),
                              "r"(b[jj * 2]), "r"(b[jj * 2 + 1]));
                    }
                }
            }
        }
    }

    const int r0 = lane >> 2;
    const int cc = (lane & 3) * 2;
    #pragma unroll
    for (int i = 0; i < 2; ++i) {
        const int mbase = m0 + wm * 32 + i * 16;
        const int mA = mbase + r0;
        const int mB = mbase + r0 + 8;
        const bool vA = (mA < M), vB = (mB < M);
        const int prA = vA ? preorder_row(mA) : 0;
        const int prB = vB ? preorder_row(mB) : 0;
        __nv_bfloat16* oA = lgout + (size_t)prA * VPAD;
        __nv_bfloat16* oB = lgout + (size_t)prB * VPAD;
        float eA = 0.0f, eB = 0.0f;
        #pragma unroll
        for (int j = 0; j < 8; ++j) {
            const int n = n0 + wn * 64 + j * 8 + cc;     // always < VPAD, even
            const bool g0 = (n < VOCAB), g1 = (n + 1 < VOCAB);
            const float bv0 = g0 ? __ldg(bias + n)     : 0.0f;
            const float bv1 = g1 ? __ldg(bias + n + 1) : 0.0f;
            float v0 = acc[i][j][0] + bv0, v1 = acc[i][j][1] + bv1;
            float v2 = acc[i][j][2] + bv0, v3 = acc[i][j][3] + bv1;
            if (vA) {
                *(__nv_bfloat162*)(oA + n) =
                    __nv_bfloat162(__float2bfloat16(v0), __float2bfloat16(v1));
                if (g0) eA += __expf(v0);
                if (g1) eA += __expf(v1);
            }
            if (vB) {
                *(__nv_bfloat162*)(oB + n) =
                    __nv_bfloat162(__float2bfloat16(v2), __float2bfloat16(v3));
                if (g0) eB += __expf(v2);
                if (g1) eB += __expf(v3);
            }
        }
        eA += __shfl_xor_sync(0xffffffffu, eA, 1);
        eA += __shfl_xor_sync(0xffffffffu, eA, 2);
        eB += __shfl_xor_sync(0xffffffffu, eB, 1);
        eB += __shfl_xor_sync(0xffffffffu, eB, 2);
        if ((lane & 3) == 0) {
            if (vA) atomicAdd(rowsum + prA, eA);
            if (vB) atomicAdd(rowsum + prB, eB);
        }
    }
}

// ---------------- small kernels (vectorized) ----------------
__global__ void cvt_root_kernel(const float* __restrict__ root) {
    int i = blockIdx.x * 256 + threadIdx.x;
    if (i < H) g_h[i] = __float2bfloat16(root[i]);
    if (blockIdx.x == 0) {
        for (int r = threadIdx.x; r < NODES; r += 256) g_rowsum[r] = 0.0f;
    }
}

// 8 elems/thread: 2x float4 load, 1x uint4 store (n divisible by 8, src contiguous)
__global__ void cvt_w8_kernel(const float* __restrict__ src, __nv_bfloat16* __restrict__ dst, int n) {
    int i = (blockIdx.x * 256 + threadIdx.x) * 8;
    if (i < n) {
        float4 v0 = *(const float4*)(src + i);
        float4 v1 = *(const float4*)(src + i + 4);
        __nv_bfloat162 p0(__float2bfloat16(v0.x), __float2bfloat16(v0.y));
        __nv_bfloat162 p1(__float2bfloat16(v0.z), __float2bfloat16(v0.w));
        __nv_bfloat162 p2(__float2bfloat16(v1.x), __float2bfloat16(v1.y));
        __nv_bfloat162 p3(__float2bfloat16(v1.z), __float2bfloat16(v1.w));
        uint4 o;
        o.x = *(uint32_t*)&p0; o.y = *(uint32_t*)&p1;
        o.z = *(uint32_t*)&p2; o.w = *(uint32_t*)&p3;
        *(uint4*)(dst + i) = o;
    }
}

// pad-convert W2v: [2048, 32001] fp32 -> [2048, VPAD] bf16, 8 elems/thread.
// src row stride 32001 (odd) -> loads MUST be scalar (still coalesced).
__global__ void cvt_pad8_kernel(const float* __restrict__ src, __nv_bfloat16* __restrict__ dst) {
    const int CPR = VPAD / 8;                  // chunks per row = 4016
    int p = blockIdx.x * 256 + threadIdx.x;
    if (p >= H2 * CPR) return;
    int r = p / CPR, pc = p - r * CPR;
    int c = pc * 8;
    const float* srow = src + (size_t)r * VOCAB;
    float v[8];
    #pragma unroll
    for (int t = 0; t < 8; ++t) v[t] = (c + t < VOCAB) ? srow[c + t] : 0.0f;
    __nv_bfloat162 p0(__float2bfloat16(v[0]), __float2bfloat16(v[1]));
    __nv_bfloat162 p1(__float2bfloat16(v[2]), __float2bfloat16(v[3]));
    __nv_bfloat162 p2(__float2bfloat16(v[4]), __float2bfloat16(v[5]));
    __nv_bfloat162 p3(__float2bfloat16(v[6]), __float2bfloat16(v[7]));
    uint4 o;
    o.x = *(uint32_t*)&p0; o.y = *(uint32_t*)&p1;
    o.z = *(uint32_t*)&p2; o.w = *(uint32_t*)&p3;
    *(uint4*)(dst + (size_t)r * VPAD + c) = o;
}

// out[r][i] = bf16_logits[r][i] - log(rowsum[r]) ; sole writer of d_out.
__global__ void __launch_bounds__(256)
lse_sub_kernel(const __nv_bfloat16* __restrict__ lg, float* __restrict__ out,
               const float* __restrict__ rowsum) {
    const int r = blockIdx.x;
    const float lse = logf(rowsum[r]);
    const __nv_bfloat16* src = lg + (size_t)r * VPAD;
    float* p = out + (size_t)r * VOCAB;
    const int tid = threadIdx.x;
    const int head = (4 - (int)(((size_t)r * VOCAB) & 3)) & 3;
    if (tid < head) p[tid] = __bfloat162float(src[tid]) - lse;
    const int nf4 = (VOCAB - head) >> 2;
    float4* p4 = (float4*)(p + head);
    for (int i = tid; i < nf4; i += 256) {
        const int o = head + i * 4;
        float4 v;
        v.x = __bfloat162float(src[o])     - lse;
        v.y = __bfloat162float(src[o + 1]) - lse;
        v.z = __bfloat162float(src[o + 2]) - lse;
        v.w = __bfloat162float(src[o + 3]) - lse;
        p4[i] = v;
    }
    const int done = head + nf4 * 4;
    if (tid < VOCAB - done) p[done + tid] = __bfloat162float(src[done + tid]) - lse;
}

// ---------------- launch ----------------
extern "C" void kernel_launch(void* const* d_in, const int* in_sizes, int n_in,
                              void* d_out, int out_size) {
    (void)in_sizes; (void)n_in; (void)out_size;
    const float* root = (const float*)d_in[0];
    const float* W1v  = (const float*)d_in[1];
    const float* b1v  = (const float*)d_in[2];
    const float* W2v  = (const float*)d_in[3];
    const float* b2v  = (const float*)d_in[4];
    const float* W1c  = (const float*)d_in[5];
    const float* b1c  = (const float*)d_in[6];
    const float* W2c  = (const float*)d_in[7];
    const float* b2c  = (const float*)d_in[8];

    void* pa;
    cudaGetSymbolAddress(&pa, g_h);      __nv_bfloat16* g_h_p    = (__nv_bfloat16*)pa;
    cudaGetSymbolAddress(&pa, g_mid);    __nv_bfloat16* g_mid_p  = (__nv_bfloat16*)pa;
    cudaGetSymbolAddress(&pa, g_W1c);    __nv_bfloat16* W1c_b    = (__nv_bfloat16*)pa;
    cudaGetSymbolAddress(&pa, g_W2c);    __nv_bfloat16* W2c_b    = (__nv_bfloat16*)pa;
    cudaGetSymbolAddress(&pa, g_W1v);    __nv_bfloat16* W1v_b    = (__nv_bfloat16*)pa;
    cudaGetSymbolAddress(&pa, g_W2v);    __nv_bfloat16* W2v_b    = (__nv_bfloat16*)pa;
    cudaGetSymbolAddress(&pa, g_logits); __nv_bfloat16* lg_p     = (__nv_bfloat16*)pa;
    cudaGetSymbolAddress(&pa, g_rowsum); float*         rowsum_p = (float*)pa;
    cudaGetSymbolAddress(&pa, g_part);   float*         part_p   = (float*)pa;

    cudaFuncSetAttribute(gemm_logits, cudaFuncAttributeMaxDynamicSharedMemorySize, L_SMEM);
    cudaFuncSetAttribute(gemm_mid64,  cudaFuncAttributeMaxDynamicSharedMemorySize, L_SMEM);

    cvt_root_kernel<<<4, 256>>>(root);
    cvt_w8_kernel<<<(H * H2 / 8 + 255) / 256, 256>>>(W1c, W1c_b, H * H2);
    cvt_w8_kernel<<<(H2 * H2 / 8 + 255) / 256, 256>>>(W2c, W2c_b, H2 * H2);
    cvt_w8_kernel<<<(H * H2 / 8 + 255) / 256, 256>>>(W1v, W1v_b, H * H2);
    cvt_pad8_kernel<<<(H2 * (VPAD / 8) + 255) / 256, 256>>>(W2v, W2v_b);

    // ---- tree expansion via split-K small GEMMs (R13 proven path) ----
    int off = 0;
    for (int d = 0; d < DEPTH; ++d) {
        const int R  = 1 << d;
        const int gx = (R + 63) / 64;
        int ks = 512 / (gx * 16);
        if (ks < 1) ks = 1;
        if (ks > 8) ks = 8;
        const int Mpad = gx * 64;
        const int fin_grid = (R * (H2 / 2) + 255) / 256;

        smallgemm<<<dim3(gx, 16, ks), 256>>>(g_h_p + (size_t)off * H, H,
                                             W1c_b, R, H / ks, part_p);
        finalize<0><<<fin_grid, 256>>>(part_p, ks, Mpad, b1c, R, 0);
        smallgemm<<<dim3(gx, 16, ks), 256>>>(g_mid_p, H2,
                                             W2c_b, R, H2 / ks, part_p);
        finalize<1><<<fin_grid, 256>>>(part_p, ks, Mpad, b2c, R, 2 * off + 1);
        off = 2 * off + 1;
    }

    // ---- vocab first layer for all nodes (BK=64 path) ----
    {
        dim3 grid((NODES + BM - 1) / BM, H2 / BN);
        gemm_mid64<<<grid, 256, L_SMEM>>>(g_h_p, W1v_b, b1v, g_mid_p);
    }

    // ---- logits GEMM -> bf16 staging + rowsum ----
    {
        dim3 grid((NODES + BM - 1) / BM, VPAD / BN);
        gemm_logits<<<grid, 256, L_SMEM>>>(g_mid_p, W2v_b, b2v,
                                           lg_p, rowsum_p);
    }

    // ---- final: out = logits - log-sum-exp (writes all of d_out) ----
    lse_sub_kernel<<<NODES, 256>>>(lg_p, (float*)d_out, rowsum_p);
}